// round 5
// baseline (speedup 1.0000x reference)
#include <cuda_runtime.h>
#include <cstdint>
#include <cstddef>

#define BATCH 2
#define SEQ   2048
#define HID   4096
#define NH    32
#define KVH   8
#define HD    128

#define CDIV(a,b) (((a)+(b)-1)/(b))

// ---------------- scratch (allocation-free: __device__ globals) ----------------
__device__ float g_Q[BATCH*SEQ*NH*HD];    // 64 MB
__device__ float g_K[BATCH*SEQ*KVH*HD];   // 16 MB
__device__ float g_V[BATCH*SEQ*KVH*HD];   // 16 MB
__device__ float g_O[BATCH*SEQ*NH*HD];    // 64 MB
__device__ float g_cos[SEQ*64];
__device__ float g_sin[SEQ*64];

// ---------------- helpers ----------------
static __device__ __forceinline__ float to_tf32(float x) {
    uint32_t u;
    asm("cvt.rna.tf32.f32 %0, %1;" : "=r"(u) : "f"(x));
    return __uint_as_float(u);
}

static __device__ __forceinline__ void mma_tf32(float* d, const uint32_t* a, const uint32_t* b) {
    asm volatile(
        "mma.sync.aligned.m16n8k8.row.col.f32.tf32.tf32.f32 "
        "{%0,%1,%2,%3}, {%4,%5,%6,%7}, {%8,%9}, {%0,%1,%2,%3};\n"
        : "+f"(d[0]), "+f"(d[1]), "+f"(d[2]), "+f"(d[3])
        : "r"(a[0]), "r"(a[1]), "r"(a[2]), "r"(a[3]),
          "r"(b[0]), "r"(b[1]));
}

// ---------------- RoPE table (double precision angles) ----------------
__global__ void rope_table_kernel(const int* __restrict__ pos,
                                  float* __restrict__ ct, float* __restrict__ st) {
    int s = blockIdx.x;
    int i = threadIdx.x;             // 0..63
    double inv = exp(-9.210340371976184 * (double)i / 64.0);  // 10000^(-2i/128)
    double ang = (double)pos[s] * inv;
    ct[s*64 + i] = (float)cos(ang);
    st[s*64 + i] = (float)sin(ang);
}

// ---------------- RoPE apply (in place) ----------------
__global__ void rope_apply_kernel(float* __restrict__ X, const float* __restrict__ ct,
                                  const float* __restrict__ st, int nh, int total) {
    int idx = blockIdx.x * blockDim.x + threadIdx.x;
    if (idx >= total) return;
    int i   = idx & 63;
    int h   = (idx >> 6) % nh;
    int row = idx / (64 * nh);        // b*SEQ + s
    int s   = row & (SEQ - 1);
    float c  = ct[s*64 + i];
    float sn = st[s*64 + i];
    size_t base = (size_t)row * ((size_t)nh * 128) + (size_t)h * 128 + i;
    float x1 = X[base];
    float x2 = X[base + 64];
    X[base]      = x1 * c - x2 * sn;
    X[base + 64] = x2 * c + x1 * sn;
}

// ---------------- TF32 tensor-core GEMM: C[M,N] = A[M,K] * B[N,K]^T ----------------
// 128x128 block tile, BK=16, 256 threads (8 warps: 2(m) x 4(n), warp tile 64x32).
// smem stride 20 floats -> conflict-free fragment LDS.
__global__ __launch_bounds__(256, 2)
void gemm_tf32_nt(const float* __restrict__ A, const float* __restrict__ B,
                  float* __restrict__ C, int M, int N, int K) {
    __shared__ float As[2][128*20];
    __shared__ float Bs[2][128*20];

    const int tid = threadIdx.x;
    const int bm0 = blockIdx.y * 128;
    const int bn0 = blockIdx.x * 128;
    const int warp = tid >> 5, lane = tid & 31;
    const int wm = warp >> 2, wn = warp & 3;      // 2 x 4
    const int g = lane >> 2, tig = lane & 3;

    const int lr = tid >> 2;                      // 0..63
    const int lc = (tid & 3) * 4;                 // 0/4/8/12
    const float* Ap = A + (size_t)(bm0 + lr) * K + lc;
    const float* Bp = B + (size_t)(bn0 + lr) * K + lc;
    const int so = lr * 20 + lc;

    float acc[4][4][4];
#pragma unroll
    for (int i = 0; i < 4; i++)
#pragma unroll
        for (int j = 0; j < 4; j++)
#pragma unroll
            for (int v = 0; v < 4; v++) acc[i][j][v] = 0.f;

    float4 ra0 = *(const float4*)Ap;
    float4 ra1 = *(const float4*)(Ap + (size_t)64 * K);
    float4 rb0 = *(const float4*)Bp;
    float4 rb1 = *(const float4*)(Bp + (size_t)64 * K);

    auto sts = [&](float* dst, float4 v) {
        float4 t;
        t.x = to_tf32(v.x); t.y = to_tf32(v.y);
        t.z = to_tf32(v.z); t.w = to_tf32(v.w);
        *(float4*)dst = t;
    };
    sts(&As[0][so], ra0); sts(&As[0][so + 64*20], ra1);
    sts(&Bs[0][so], rb0); sts(&Bs[0][so + 64*20], rb1);
    __syncthreads();

    const int iters = K >> 4;
    int buf = 0;
    for (int t = 0; t < iters; t++) {
        if (t + 1 < iters) {
            const float* Ap2 = Ap + (t + 1) * 16;
            const float* Bp2 = Bp + (t + 1) * 16;
            ra0 = *(const float4*)Ap2;
            ra1 = *(const float4*)(Ap2 + (size_t)64 * K);
            rb0 = *(const float4*)Bp2;
            rb1 = *(const float4*)(Bp2 + (size_t)64 * K);
        }
        const float* asb = As[buf];
        const float* bsb = Bs[buf];
#pragma unroll
        for (int kk = 0; kk < 16; kk += 8) {
            uint32_t af[4][4], bf[4][2];
#pragma unroll
            for (int mt = 0; mt < 4; mt++) {
                int m = wm * 64 + mt * 16 + g;
                af[mt][0] = __float_as_uint(asb[m * 20 + kk + tig]);
                af[mt][1] = __float_as_uint(asb[(m + 8) * 20 + kk + tig]);
                af[mt][2] = __float_as_uint(asb[m * 20 + kk + tig + 4]);
                af[mt][3] = __float_as_uint(asb[(m + 8) * 20 + kk + tig + 4]);
            }
#pragma unroll
            for (int nt = 0; nt < 4; nt++) {
                int n = wn * 32 + nt * 8 + g;
                bf[nt][0] = __float_as_uint(bsb[n * 20 + kk + tig]);
                bf[nt][1] = __float_as_uint(bsb[n * 20 + kk + tig + 4]);
            }
#pragma unroll
            for (int mt = 0; mt < 4; mt++)
#pragma unroll
                for (int nt = 0; nt < 4; nt++)
                    mma_tf32(acc[mt][nt], af[mt], bf[nt]);
        }
        if (t + 1 < iters) {
            int nb = buf ^ 1;
            sts(&As[nb][so], ra0); sts(&As[nb][so + 64*20], ra1);
            sts(&Bs[nb][so], rb0); sts(&Bs[nb][so + 64*20], rb1);
        }
        __syncthreads();
        buf ^= 1;
    }

#pragma unroll
    for (int mt = 0; mt < 4; mt++) {
        int row = bm0 + wm * 64 + mt * 16 + g;
#pragma unroll
        for (int nt = 0; nt < 4; nt++) {
            int col = bn0 + wn * 32 + nt * 8 + tig * 2;
            *(float2*)&C[(size_t)row * N + col] =
                make_float2(acc[mt][nt][0], acc[mt][nt][1]);
            *(float2*)&C[(size_t)(row + 8) * N + col] =
                make_float2(acc[mt][nt][2], acc[mt][nt][3]);
        }
    }
}

// ---------------- Flash attention (causal, GQA), tf32 mma ----------------
// Block: 128 threads (4 warps), 64 query rows (16 per warp), key tiles of 64, D=128.
// smem: Ks[64][132], Vs[64][136], Qs/Ps[64][132]  (strides chosen conflict-free)
#define FST  132
#define FSTV 136
#define FLASH_SMEM ((64*FST + 64*FSTV + 64*FST) * 4)

__global__ __launch_bounds__(128)
void flash_kernel(const float* __restrict__ Q, const float* __restrict__ K,
                  const float* __restrict__ V, float* __restrict__ O) {
    extern __shared__ float sm[];
    float* Ks = sm;
    float* Vs = sm + 64 * FST;
    float* Qs = sm + 64 * FST + 64 * FSTV;   // reused as Ps after prologue

    const int tid = threadIdx.x;
    const int w = tid >> 5, lane = tid & 31;
    const int g = lane >> 2, tig = lane & 3;
    const int qb  = blockIdx.x;               // 0..31
    const int bh  = blockIdx.y;               // 0..63
    const int b   = bh >> 5;
    const int h   = bh & 31;
    const int kvh = h >> 2;                   // GROUPS=4 consecutive
    const int qm0 = qb * 64;

    const float* Qb = Q + (size_t)b * SEQ * HID + (size_t)h * 128;
    const float* Kb = K + (size_t)b * SEQ * (KVH*HD) + (size_t)kvh * 128;
    const float* Vb = V + (size_t)b * SEQ * (KVH*HD) + (size_t)kvh * 128;

    // --- load Q tile, tf32-rounded ---
    for (int i = tid; i < 64 * 32; i += 128) {
        int r = i >> 5, c4 = (i & 31) * 4;
        float4 v = *(const float4*)(Qb + (size_t)(qm0 + r) * HID + c4);
        float4 t;
        t.x = to_tf32(v.x); t.y = to_tf32(v.y);
        t.z = to_tf32(v.z); t.w = to_tf32(v.w);
        *(float4*)(Qs + r * FST + c4) = t;
    }
    __syncthreads();

    // --- Q fragments -> registers (this warp's 16 rows) ---
    uint32_t qf[16][4];
#pragma unroll
    for (int ks = 0; ks < 16; ks++) {
        int r0 = (w * 16 + g) * FST + ks * 8 + tig;
        int r1 = (w * 16 + g + 8) * FST + ks * 8 + tig;
        qf[ks][0] = __float_as_uint(Qs[r0]);
        qf[ks][1] = __float_as_uint(Qs[r1]);
        qf[ks][2] = __float_as_uint(Qs[r0 + 4]);
        qf[ks][3] = __float_as_uint(Qs[r1 + 4]);
    }
    float* Ps = Qs;   // Q smem reused for P (per-warp-private rows)

    float oacc[16][4];
#pragma unroll
    for (int i = 0; i < 16; i++)
#pragma unroll
        for (int v = 0; v < 4; v++) oacc[i][v] = 0.f;
    float m0 = -1e30f, m1 = -1e30f, l0 = 0.f, l1 = 0.f;

    const float scale = 0.08838834764831845f;  // 1/sqrt(128)

    for (int kj = 0; kj <= qb; kj++) {
        // --- load K/V tiles (tf32 for both: QK^T and PV are tf32 mmas) ---
        for (int i = tid; i < 64 * 32; i += 128) {
            int r = i >> 5, c4 = (i & 31) * 4;
            size_t goff = (size_t)(kj * 64 + r) * (KVH*HD) + c4;
            float4 kv = *(const float4*)(Kb + goff);
            float4 vv = *(const float4*)(Vb + goff);
            float4 tk, tv;
            tk.x = to_tf32(kv.x); tk.y = to_tf32(kv.y);
            tk.z = to_tf32(kv.z); tk.w = to_tf32(kv.w);
            tv.x = to_tf32(vv.x); tv.y = to_tf32(vv.y);
            tv.z = to_tf32(vv.z); tv.w = to_tf32(vv.w);
            *(float4*)(Ks + r * FST  + c4) = tk;
            *(float4*)(Vs + r * FSTV + c4) = tv;
        }
        __syncthreads();

        // --- S = Q K^T  (16 x 64 per warp) ---
        float sf[8][4];
#pragma unroll
        for (int nt = 0; nt < 8; nt++)
#pragma unroll
            for (int v = 0; v < 4; v++) sf[nt][v] = 0.f;

#pragma unroll
        for (int ks = 0; ks < 16; ks++) {
#pragma unroll
            for (int nt = 0; nt < 8; nt++) {
                uint32_t bf[2];
                int ka = (nt * 8 + g) * FST + ks * 8 + tig;
                bf[0] = __float_as_uint(Ks[ka]);
                bf[1] = __float_as_uint(Ks[ka + 4]);
                mma_tf32(sf[nt], qf[ks], bf);
            }
        }

        // --- scale + causal mask ---
#pragma unroll
        for (int nt = 0; nt < 8; nt++)
#pragma unroll
            for (int v = 0; v < 4; v++) sf[nt][v] *= scale;

        const int q0 = qm0 + w * 16 + g;
        const int q1 = q0 + 8;
        if (kj == qb) {
#pragma unroll
            for (int nt = 0; nt < 8; nt++) {
                int k0 = kj * 64 + nt * 8 + tig * 2;
                if (k0     > q0) sf[nt][0] = -1e30f;
                if (k0 + 1 > q0) sf[nt][1] = -1e30f;
                if (k0     > q1) sf[nt][2] = -1e30f;
                if (k0 + 1 > q1) sf[nt][3] = -1e30f;
            }
        }

        // --- online softmax update ---
        float rm0 = -1e30f, rm1 = -1e30f;
#pragma unroll
        for (int nt = 0; nt < 8; nt++) {
            rm0 = fmaxf(rm0, fmaxf(sf[nt][0], sf[nt][1]));
            rm1 = fmaxf(rm1, fmaxf(sf[nt][2], sf[nt][3]));
        }
        rm0 = fmaxf(rm0, __shfl_xor_sync(0xffffffffu, rm0, 1));
        rm0 = fmaxf(rm0, __shfl_xor_sync(0xffffffffu, rm0, 2));
        rm1 = fmaxf(rm1, __shfl_xor_sync(0xffffffffu, rm1, 1));
        rm1 = fmaxf(rm1, __shfl_xor_sync(0xffffffffu, rm1, 2));

        float mn0 = fmaxf(m0, rm0), mn1 = fmaxf(m1, rm1);
        float a0 = __expf(m0 - mn0), a1 = __expf(m1 - mn1);
        float rs0 = 0.f, rs1 = 0.f;
#pragma unroll
        for (int nt = 0; nt < 8; nt++) {
            sf[nt][0] = __expf(sf[nt][0] - mn0); rs0 += sf[nt][0];
            sf[nt][1] = __expf(sf[nt][1] - mn0); rs0 += sf[nt][1];
            sf[nt][2] = __expf(sf[nt][2] - mn1); rs1 += sf[nt][2];
            sf[nt][3] = __expf(sf[nt][3] - mn1); rs1 += sf[nt][3];
        }
        rs0 += __shfl_xor_sync(0xffffffffu, rs0, 1);
        rs0 += __shfl_xor_sync(0xffffffffu, rs0, 2);
        rs1 += __shfl_xor_sync(0xffffffffu, rs1, 1);
        rs1 += __shfl_xor_sync(0xffffffffu, rs1, 2);

        l0 = l0 * a0 + rs0;
        l1 = l1 * a1 + rs1;
        m0 = mn0; m1 = mn1;

#pragma unroll
        for (int nt = 0; nt < 16; nt++) {
            oacc[nt][0] *= a0; oacc[nt][1] *= a0;
            oacc[nt][2] *= a1; oacc[nt][3] *= a1;
        }

        // --- write P (tf32) to this warp's rows of Ps ---
        const int pr0 = (w * 16 + g) * FST;
        const int pr1 = (w * 16 + g + 8) * FST;
#pragma unroll
        for (int nt = 0; nt < 8; nt++) {
            int c = nt * 8 + tig * 2;
            *(float2*)&Ps[pr0 + c] = make_float2(to_tf32(sf[nt][0]), to_tf32(sf[nt][1]));
            *(float2*)&Ps[pr1 + c] = make_float2(to_tf32(sf[nt][2]), to_tf32(sf[nt][3]));
        }
        __syncwarp();

        // --- O += P @ V  (16 x 128 per warp) ---
#pragma unroll
        for (int ks = 0; ks < 8; ks++) {
            uint32_t pa[4];
            pa[0] = __float_as_uint(Ps[pr0 + ks * 8 + tig]);
            pa[1] = __float_as_uint(Ps[pr1 + ks * 8 + tig]);
            pa[2] = __float_as_uint(Ps[pr0 + ks * 8 + tig + 4]);
            pa[3] = __float_as_uint(Ps[pr1 + ks * 8 + tig + 4]);
#pragma unroll
            for (int nt = 0; nt < 16; nt++) {
                uint32_t vb[2];
                vb[0] = __float_as_uint(Vs[(ks * 8 + tig) * FSTV + nt * 8 + g]);
                vb[1] = __float_as_uint(Vs[(ks * 8 + tig + 4) * FSTV + nt * 8 + g]);
                mma_tf32(oacc[nt], pa, vb);
            }
        }
        __syncthreads();   // before next K/V tile overwrite
    }

    // --- normalize + store ---
    float il0 = 1.f / l0, il1 = 1.f / l1;
    size_t ro0 = ((size_t)(b * SEQ + qm0 + w * 16 + g)) * HID + (size_t)h * 128;
    size_t ro1 = ro0 + (size_t)8 * HID;
#pragma unroll
    for (int nt = 0; nt < 16; nt++) {
        int c = nt * 8 + tig * 2;
        *(float2*)&O[ro0 + c] = make_float2(oacc[nt][0] * il0, oacc[nt][1] * il0);
        *(float2*)&O[ro1 + c] = make_float2(oacc[nt][2] * il1, oacc[nt][3] * il1);
    }
}

// ---------------- launch ----------------
extern "C" void kernel_launch(void* const* d_in, const int* in_sizes, int n_in,
                              void* d_out, int out_size) {
    const float* hidden = (const float*)d_in[0];
    const int*   pos    = (const int*)d_in[1];
    const float* Wq     = (const float*)d_in[2];
    const float* Wk     = (const float*)d_in[3];
    const float* Wv     = (const float*)d_in[4];
    const float* Wo     = (const float*)d_in[5];
    float* out = (float*)d_out;

    float *pQ, *pK, *pV, *pO, *pc, *ps;
    cudaGetSymbolAddress((void**)&pQ, g_Q);
    cudaGetSymbolAddress((void**)&pK, g_K);
    cudaGetSymbolAddress((void**)&pV, g_V);
    cudaGetSymbolAddress((void**)&pO, g_O);
    cudaGetSymbolAddress((void**)&pc, g_cos);
    cudaGetSymbolAddress((void**)&ps, g_sin);

    cudaFuncSetAttribute(flash_kernel,
                         cudaFuncAttributeMaxDynamicSharedMemorySize, FLASH_SMEM);

    const int M = BATCH * SEQ;   // 4096

    // RoPE tables
    rope_table_kernel<<<SEQ, 64>>>(pos, pc, ps);

    // Q/K/V projections
    dim3 gq(HID / 128, M / 128);             // (32,32)
    dim3 gk((KVH * HD) / 128, M / 128);      // (8,32)
    gemm_tf32_nt<<<gq, 256>>>(hidden, Wq, pQ, M, NH * HD, HID);
    gemm_tf32_nt<<<gk, 256>>>(hidden, Wk, pK, M, KVH * HD, HID);
    gemm_tf32_nt<<<gk, 256>>>(hidden, Wv, pV, M, KVH * HD, HID);

    // RoPE
    int tq = M * NH * 64;
    int tk = M * KVH * 64;
    rope_apply_kernel<<<CDIV(tq, 256), 256>>>(pQ, pc, ps, NH, tq);
    rope_apply_kernel<<<CDIV(tk, 256), 256>>>(pK, pc, ps, KVH, tk);

    // attention
    dim3 gf(SEQ / 64, BATCH * NH);           // (32,64)
    flash_kernel<<<gf, 128, FLASH_SMEM>>>(pQ, pK, pV, pO);

    // output projection -> d_out
    gemm_tf32_nt<<<gq, 256>>>(pO, Wo, out, M, HID, HID);
}

// round 8
// speedup vs baseline: 1.9873x; 1.9873x over previous
#include <cuda_runtime.h>
#include <cuda_fp16.h>
#include <cstdint>
#include <cstddef>

#define BATCH 2
#define SEQ   2048
#define HID   4096
#define NH    32
#define KVH   8
#define HD    128
#define MTOT  (BATCH*SEQ)      // 4096
#define KVD   (KVH*HD)         // 1024

#define CDIV(a,b) (((a)+(b)-1)/(b))

// ---------------- scratch (allocation-free: __device__ globals) ----------------
__device__ __half g_Ah [MTOT*HID];     // fp16(hidden)
__device__ __half g_Wqh[HID*HID];
__device__ __half g_Wkh[KVD*HID];
__device__ __half g_Wvh[KVD*HID];
__device__ __half g_Woh[HID*HID];
__device__ __half g_Qh [MTOT*HID];
__device__ __half g_Kh [MTOT*KVD];
__device__ __half g_Vh [MTOT*KVD];
__device__ __half g_Oh [MTOT*HID];
__device__ float  g_cos[SEQ*64];
__device__ float  g_sin[SEQ*64];

// ---------------- helpers ----------------
static __device__ __forceinline__ uint32_t smem_u32(const void* p) {
    uint32_t a;
    asm("{ .reg .u64 t; cvta.to.shared.u64 t, %1; cvt.u32.u64 %0, t; }" : "=r"(a) : "l"(p));
    return a;
}

static __device__ __forceinline__ void mma_f16(float* d, const uint32_t* a, const uint32_t* b) {
    asm volatile(
        "mma.sync.aligned.m16n8k16.row.col.f32.f16.f16.f32 "
        "{%0,%1,%2,%3}, {%4,%5,%6,%7}, {%8,%9}, {%0,%1,%2,%3};\n"
        : "+f"(d[0]), "+f"(d[1]), "+f"(d[2]), "+f"(d[3])
        : "r"(a[0]), "r"(a[1]), "r"(a[2]), "r"(a[3]),
          "r"(b[0]), "r"(b[1]));
}

static __device__ __forceinline__ void ldsm_x4(uint32_t* r, uint32_t addr) {
    asm volatile("ldmatrix.sync.aligned.m8n8.x4.shared.b16 {%0,%1,%2,%3}, [%4];"
                 : "=r"(r[0]), "=r"(r[1]), "=r"(r[2]), "=r"(r[3]) : "r"(addr));
}
static __device__ __forceinline__ void ldsm_x4t(uint32_t* r, uint32_t addr) {
    asm volatile("ldmatrix.sync.aligned.m8n8.x4.trans.shared.b16 {%0,%1,%2,%3}, [%4];"
                 : "=r"(r[0]), "=r"(r[1]), "=r"(r[2]), "=r"(r[3]) : "r"(addr));
}

static __device__ __forceinline__ void cp_async16(uint32_t dst, const void* src) {
    asm volatile("cp.async.cg.shared.global [%0], [%1], 16;" :: "r"(dst), "l"(src));
}
static __device__ __forceinline__ void cp_commit() {
    asm volatile("cp.async.commit_group;" ::: "memory");
}
template<int N> static __device__ __forceinline__ void cp_wait() {
    asm volatile("cp.async.wait_group %0;" :: "n"(N) : "memory");
}

static __device__ __forceinline__ uint32_t pack_h2(float a, float b) {
    __half2 h = __floats2half2_rn(a, b);
    return *reinterpret_cast<uint32_t*>(&h);
}

// ---------------- fp32 -> fp16 convert (8 elts/thread) ----------------
__global__ void f2h_kernel(const float4* __restrict__ in, uint4* __restrict__ out, int n8) {
    int i = blockIdx.x * blockDim.x + threadIdx.x;
    if (i >= n8) return;
    float4 a = in[2*i], b = in[2*i+1];
    uint4 o;
    o.x = pack_h2(a.x, a.y); o.y = pack_h2(a.z, a.w);
    o.z = pack_h2(b.x, b.y); o.w = pack_h2(b.z, b.w);
    out[i] = o;
}

// ---------------- RoPE ----------------
__global__ void rope_table_kernel(const int* __restrict__ pos,
                                  float* __restrict__ ct, float* __restrict__ st) {
    int s = blockIdx.x;
    int i = threadIdx.x;             // 0..63
    double inv = exp(-9.210340371976184 * (double)i / 64.0);  // 10000^(-2i/128)
    double ang = (double)pos[s] * inv;
    ct[s*64 + i] = (float)cos(ang);
    st[s*64 + i] = (float)sin(ang);
}

__global__ void rope_h_kernel(__half* __restrict__ X, const float* __restrict__ ct,
                              const float* __restrict__ st, int nh, int total) {
    int idx = blockIdx.x * blockDim.x + threadIdx.x;
    if (idx >= total) return;
    int i   = idx & 63;
    int h   = (idx >> 6) % nh;
    int row = idx / (64 * nh);        // b*SEQ + s
    int s   = row & (SEQ - 1);
    float c  = ct[s*64 + i];
    float sn = st[s*64 + i];
    size_t base = (size_t)row * ((size_t)nh * 128) + (size_t)h * 128 + i;
    float x1 = __half2float(X[base]);
    float x2 = __half2float(X[base + 64]);
    X[base]      = __float2half_rn(x1 * c - x2 * sn);
    X[base + 64] = __float2half_rn(x2 * c + x1 * sn);
}

// ============== fp16 tensor-core GEMM: C[M,N] = A[M,K] * B[N,K]^T ==============
// CTA 128x256, 8 warps (2x4) of 64x64, BK=32, 4-stage cp.async, ldmatrix frags.
#define GBM 128
#define GBN 256
#define GBK 32
#define GSTG 4
#define GST 40                               // halves per row (32 + 8 pad); 80B, 16B aligned
#define A_BYTES (GBM*GST*2)                  // 10240
#define B_BYTES (GBN*GST*2)                  // 20480
#define STG_BYTES (A_BYTES + B_BYTES)        // 30720
#define GEMM_SMEM (GSTG*STG_BYTES)           // 122880

template<bool HALF_OUT>
__global__ __launch_bounds__(256, 1)
void gemm_h(const __half* __restrict__ A, const __half* __restrict__ B,
            void* __restrict__ Cout, int N, int K) {
    extern __shared__ char smem[];
    const uint32_t sb = smem_u32(smem);
    const int tid = threadIdx.x, lane = tid & 31, warp = tid >> 5;
    const int wm = warp >> 2, wn = warp & 3;          // 2 x 4
    const int g = lane >> 2, tig = lane & 3;
    const int bm0 = blockIdx.y * GBM, bn0 = blockIdx.x * GBN;
    const __half* Ab = A + (size_t)bm0 * K;
    const __half* Bb = B + (size_t)bn0 * K;

    auto load_stage = [&](int s, int kt) {
        uint32_t stg = sb + s * STG_BYTES;
#pragma unroll
        for (int j = 0; j < 6; j++) {
            int ci = tid + j * 256;
            uint32_t dst; const __half* src;
            if (ci < 512) {
                int r = ci >> 2, c = ci & 3;
                dst = stg + (uint32_t)(r * (GST*2) + c * 16);
                src = Ab + (size_t)r * K + kt * GBK + c * 8;
            } else {
                int li = ci - 512;
                int r = li >> 2, c = li & 3;
                dst = stg + A_BYTES + (uint32_t)(r * (GST*2) + c * 16);
                src = Bb + (size_t)r * K + kt * GBK + c * 8;
            }
            cp_async16(dst, src);
        }
        cp_commit();
    };

    float acc[4][8][4];
#pragma unroll
    for (int i = 0; i < 4; i++)
#pragma unroll
        for (int j = 0; j < 8; j++)
#pragma unroll
            for (int v = 0; v < 4; v++) acc[i][j][v] = 0.f;

    const int NIT = K / GBK;   // 128
    load_stage(0, 0);
    load_stage(1, 1);
    load_stage(2, 2);

    for (int it = 0; it < NIT; it++) {
        int s = it & 3;
        cp_wait<2>();
        __syncthreads();
        if (it + 3 < NIT) load_stage((it + 3) & 3, it + 3);
        else cp_commit();

        uint32_t As = sb + s * STG_BYTES;
        uint32_t Bs = As + A_BYTES;
#pragma unroll
        for (int kg = 0; kg < 2; kg++) {
            int kk = kg * 16;
            uint32_t af[4][4], bf[8][2];
#pragma unroll
            for (int mt = 0; mt < 4; mt++) {
                uint32_t row = (uint32_t)(wm * 64 + mt * 16 + (lane & 7) + ((lane >> 3) & 1) * 8);
                uint32_t col = (uint32_t)(kk + ((lane >> 4) & 1) * 8);
                ldsm_x4(af[mt], As + row * (GST*2) + col * 2);
            }
#pragma unroll
            for (int np = 0; np < 4; np++) {
                uint32_t row = (uint32_t)(wn * 64 + np * 16 + (lane & 7) + ((lane >> 4) & 1) * 8);
                uint32_t col = (uint32_t)(kk + ((lane >> 3) & 1) * 8);
                uint32_t t[4];
                ldsm_x4(t, Bs + row * (GST*2) + col * 2);
                bf[np*2][0] = t[0]; bf[np*2][1] = t[1];
                bf[np*2+1][0] = t[2]; bf[np*2+1][1] = t[3];
            }
#pragma unroll
            for (int mt = 0; mt < 4; mt++)
#pragma unroll
                for (int nt = 0; nt < 8; nt++)
                    mma_f16(acc[mt][nt], af[mt], bf[nt]);
        }
    }

    // epilogue
#pragma unroll
    for (int mt = 0; mt < 4; mt++) {
        int r0 = bm0 + wm * 64 + mt * 16 + g;
#pragma unroll
        for (int nt = 0; nt < 8; nt++) {
            int c = bn0 + wn * 64 + nt * 8 + tig * 2;
            if (HALF_OUT) {
                __half2* C = (__half2*)Cout;
                C[((size_t)r0 * N + c) >> 1] =
                    __floats2half2_rn(acc[mt][nt][0], acc[mt][nt][1]);
                C[((size_t)(r0 + 8) * N + c) >> 1] =
                    __floats2half2_rn(acc[mt][nt][2], acc[mt][nt][3]);
            } else {
                float* C = (float*)Cout;
                *(float2*)&C[(size_t)r0 * N + c] = make_float2(acc[mt][nt][0], acc[mt][nt][1]);
                *(float2*)&C[(size_t)(r0 + 8) * N + c] = make_float2(acc[mt][nt][2], acc[mt][nt][3]);
            }
        }
    }
}

// ============== fp16 flash attention (causal, GQA) ==============
// 4 warps, 64 q rows (16/warp), kv tiles of 64, D=128. P stays in registers.
// smem: K0,V0,K1,V1 (double-buffered), Q — each 64 x 136 halves.
#define FQS 136
#define FTILE (64*FQS)                 // halves
#define FLASH_SMEM (FTILE*5*2)         // 87040 B

__global__ __launch_bounds__(128, 1)
void flash_h(const __half* __restrict__ Q, const __half* __restrict__ K,
             const __half* __restrict__ V, __half* __restrict__ O) {
    extern __shared__ char fsm[];
    const uint32_t sb = smem_u32(fsm);
    const uint32_t KsA[2] = {sb,              sb + 2*FTILE*2};
    const uint32_t VsA[2] = {sb + FTILE*2,    sb + 3*FTILE*2};
    const uint32_t QsA    =  sb + 4*FTILE*2;

    const int tid = threadIdx.x;
    const int w = tid >> 5, lane = tid & 31;
    const int g = lane >> 2, tig = lane & 3;
    const int qb  = blockIdx.x;               // 0..31
    const int bh  = blockIdx.y;               // 0..63
    const int b   = bh >> 5;
    const int h   = bh & 31;
    const int kvh = h >> 2;                   // GROUPS=4 consecutive
    const int qm0 = qb * 64;

    const __half* Qb = Q + (size_t)b * SEQ * HID + (size_t)h * 128;
    const __half* Kb = K + (size_t)b * SEQ * KVD + (size_t)kvh * 128;
    const __half* Vb = V + (size_t)b * SEQ * KVD + (size_t)kvh * 128;

    // Q tile: 64 rows x 128 halves = 1024 chunks
#pragma unroll
    for (int j = 0; j < 8; j++) {
        int ci = tid + j * 128;
        int r = ci >> 4, c = ci & 15;
        cp_async16(QsA + (uint32_t)(r * (FQS*2) + c * 16),
                   Qb + (size_t)(qm0 + r) * HID + c * 8);
    }
    cp_commit();

    auto load_kv = [&](int s, int kt) {
#pragma unroll
        for (int j = 0; j < 16; j++) {
            int ci = tid + j * 128;
            bool isK = ci < 1024;
            int li = isK ? ci : ci - 1024;
            int r = li >> 4, c = li & 15;
            uint32_t dst = (isK ? KsA[s] : VsA[s]) + (uint32_t)(r * (FQS*2) + c * 16);
            const __half* src = (isK ? Kb : Vb) + (size_t)(kt * 64 + r) * KVD + c * 8;
            cp_async16(dst, src);
        }
        cp_commit();
    };

    load_kv(0, 0);

    cp_wait<1>();            // Q loaded (KV0 may still be in flight)
    __syncthreads();

    // Q fragments (this warp's 16 rows), persistent
    uint32_t qf[8][4];
#pragma unroll
    for (int kg = 0; kg < 8; kg++) {
        uint32_t row = (uint32_t)(w * 16 + (lane & 7) + ((lane >> 3) & 1) * 8);
        uint32_t col = (uint32_t)(kg * 16 + ((lane >> 4) & 1) * 8);
        ldsm_x4(qf[kg], QsA + row * (FQS*2) + col * 2);
    }

    float oacc[16][4];
#pragma unroll
    for (int i = 0; i < 16; i++)
#pragma unroll
        for (int v = 0; v < 4; v++) oacc[i][v] = 0.f;
    float m0 = -1e30f, m1 = -1e30f, l0 = 0.f, l1 = 0.f;
    const float scale = 0.08838834764831845f;  // 1/sqrt(128)

    for (int kj = 0; kj <= qb; kj++) {
        const int bf = kj & 1;
        if (kj < qb) load_kv(bf ^ 1, kj + 1);
        else cp_commit();
        cp_wait<1>();         // current tile's loads complete
        __syncthreads();

        // ---- S = Q K^T ----
        float sacc[8][4];
#pragma unroll
        for (int nt = 0; nt < 8; nt++)
#pragma unroll
            for (int v = 0; v < 4; v++) sacc[nt][v] = 0.f;

#pragma unroll
        for (int kg = 0; kg < 8; kg++) {
            uint32_t kf[8][2];
#pragma unroll
            for (int np = 0; np < 4; np++) {
                uint32_t row = (uint32_t)(np * 16 + (lane & 7) + ((lane >> 4) & 1) * 8);
                uint32_t col = (uint32_t)(kg * 16 + ((lane >> 3) & 1) * 8);
                uint32_t t[4];
                ldsm_x4(t, KsA[bf] + row * (FQS*2) + col * 2);
                kf[np*2][0] = t[0]; kf[np*2][1] = t[1];
                kf[np*2+1][0] = t[2]; kf[np*2+1][1] = t[3];
            }
#pragma unroll
            for (int nt = 0; nt < 8; nt++)
                mma_f16(sacc[nt], qf[kg], kf[nt]);
        }

        // ---- scale + causal mask ----
#pragma unroll
        for (int nt = 0; nt < 8; nt++)
#pragma unroll
            for (int v = 0; v < 4; v++) sacc[nt][v] *= scale;

        const int q0 = qm0 + w * 16 + g;
        const int q1 = q0 + 8;
        if (kj == qb) {
#pragma unroll
            for (int nt = 0; nt < 8; nt++) {
                int k0 = kj * 64 + nt * 8 + tig * 2;
                if (k0     > q0) sacc[nt][0] = -1e30f;
                if (k0 + 1 > q0) sacc[nt][1] = -1e30f;
                if (k0     > q1) sacc[nt][2] = -1e30f;
                if (k0 + 1 > q1) sacc[nt][3] = -1e30f;
            }
        }

        // ---- online softmax ----
        float rm0 = -1e30f, rm1 = -1e30f;
#pragma unroll
        for (int nt = 0; nt < 8; nt++) {
            rm0 = fmaxf(rm0, fmaxf(sacc[nt][0], sacc[nt][1]));
            rm1 = fmaxf(rm1, fmaxf(sacc[nt][2], sacc[nt][3]));
        }
        rm0 = fmaxf(rm0, __shfl_xor_sync(0xffffffffu, rm0, 1));
        rm0 = fmaxf(rm0, __shfl_xor_sync(0xffffffffu, rm0, 2));
        rm1 = fmaxf(rm1, __shfl_xor_sync(0xffffffffu, rm1, 1));
        rm1 = fmaxf(rm1, __shfl_xor_sync(0xffffffffu, rm1, 2));

        float mn0 = fmaxf(m0, rm0), mn1 = fmaxf(m1, rm1);
        float a0 = __expf(m0 - mn0), a1 = __expf(m1 - mn1);
        float rs0 = 0.f, rs1 = 0.f;
#pragma unroll
        for (int nt = 0; nt < 8; nt++) {
            sacc[nt][0] = __expf(sacc[nt][0] - mn0); rs0 += sacc[nt][0];
            sacc[nt][1] = __expf(sacc[nt][1] - mn0); rs0 += sacc[nt][1];
            sacc[nt][2] = __expf(sacc[nt][2] - mn1); rs1 += sacc[nt][2];
            sacc[nt][3] = __expf(sacc[nt][3] - mn1); rs1 += sacc[nt][3];
        }
        rs0 += __shfl_xor_sync(0xffffffffu, rs0, 1);
        rs0 += __shfl_xor_sync(0xffffffffu, rs0, 2);
        rs1 += __shfl_xor_sync(0xffffffffu, rs1, 1);
        rs1 += __shfl_xor_sync(0xffffffffu, rs1, 2);

        l0 = l0 * a0 + rs0;
        l1 = l1 * a1 + rs1;
        m0 = mn0; m1 = mn1;

#pragma unroll
        for (int nt = 0; nt < 16; nt++) {
            oacc[nt][0] *= a0; oacc[nt][1] *= a0;
            oacc[nt][2] *= a1; oacc[nt][3] *= a1;
        }

        // ---- P -> fp16 in registers (FA-2 layout trick) ----
        uint32_t pf[8][2];
#pragma unroll
        for (int nt = 0; nt < 8; nt++) {
            pf[nt][0] = pack_h2(sacc[nt][0], sacc[nt][1]);   // row g
            pf[nt][1] = pack_h2(sacc[nt][2], sacc[nt][3]);   // row g+8
        }

        // ---- O += P @ V ----
#pragma unroll
        for (int kg = 0; kg < 4; kg++) {
            uint32_t pa[4] = { pf[2*kg][0], pf[2*kg][1], pf[2*kg+1][0], pf[2*kg+1][1] };
#pragma unroll
            for (int dp = 0; dp < 8; dp++) {
                uint32_t row = (uint32_t)(kg * 16 + (lane & 7) + ((lane >> 3) & 1) * 8);
                uint32_t col = (uint32_t)(dp * 16 + ((lane >> 4) & 1) * 8);
                uint32_t t[4];
                ldsm_x4t(t, VsA[bf] + row * (FQS*2) + col * 2);
                uint32_t b0[2] = { t[0], t[1] };
                uint32_t b1[2] = { t[2], t[3] };
                mma_f16(oacc[dp*2],   pa, b0);
                mma_f16(oacc[dp*2+1], pa, b1);
            }
        }
        __syncthreads();   // all warps done with buf before it is refilled
    }

    // ---- normalize + store fp16 O ----
    float il0 = 1.f / l0, il1 = 1.f / l1;
    size_t ro0 = ((size_t)(b * SEQ + qm0 + w * 16 + g)) * HID + (size_t)h * 128;
    size_t ro1 = ro0 + (size_t)8 * HID;
#pragma unroll
    for (int nt = 0; nt < 16; nt++) {
        int c = nt * 8 + tig * 2;
        *(__half2*)&O[ro0 + c] = __floats2half2_rn(oacc[nt][0] * il0, oacc[nt][1] * il0);
        *(__half2*)&O[ro1 + c] = __floats2half2_rn(oacc[nt][2] * il1, oacc[nt][3] * il1);
    }
}

// ---------------- launch ----------------
extern "C" void kernel_launch(void* const* d_in, const int* in_sizes, int n_in,
                              void* d_out, int out_size) {
    const float* hidden = (const float*)d_in[0];
    const int*   pos    = (const int*)d_in[1];
    const float* Wq     = (const float*)d_in[2];
    const float* Wk     = (const float*)d_in[3];
    const float* Wv     = (const float*)d_in[4];
    const float* Wo     = (const float*)d_in[5];
    float* out = (float*)d_out;

    __half *pAh, *pWqh, *pWkh, *pWvh, *pWoh, *pQh, *pKh, *pVh, *pOh;
    float *pc, *ps;
    cudaGetSymbolAddress((void**)&pAh,  g_Ah);
    cudaGetSymbolAddress((void**)&pWqh, g_Wqh);
    cudaGetSymbolAddress((void**)&pWkh, g_Wkh);
    cudaGetSymbolAddress((void**)&pWvh, g_Wvh);
    cudaGetSymbolAddress((void**)&pWoh, g_Woh);
    cudaGetSymbolAddress((void**)&pQh,  g_Qh);
    cudaGetSymbolAddress((void**)&pKh,  g_Kh);
    cudaGetSymbolAddress((void**)&pVh,  g_Vh);
    cudaGetSymbolAddress((void**)&pOh,  g_Oh);
    cudaGetSymbolAddress((void**)&pc,   g_cos);
    cudaGetSymbolAddress((void**)&ps,   g_sin);

    cudaFuncSetAttribute(gemm_h<true>,
                         cudaFuncAttributeMaxDynamicSharedMemorySize, GEMM_SMEM);
    cudaFuncSetAttribute(gemm_h<false>,
                         cudaFuncAttributeMaxDynamicSharedMemorySize, GEMM_SMEM);
    cudaFuncSetAttribute(flash_h,
                         cudaFuncAttributeMaxDynamicSharedMemorySize, FLASH_SMEM);

    // RoPE tables
    rope_table_kernel<<<SEQ, 64>>>(pos, pc, ps);

    // fp32 -> fp16 converts
    {
        int n8;
        n8 = (MTOT * HID) / 8;
        f2h_kernel<<<CDIV(n8, 256), 256>>>((const float4*)hidden, (uint4*)pAh, n8);
        n8 = (HID * HID) / 8;
        f2h_kernel<<<CDIV(n8, 256), 256>>>((const float4*)Wq, (uint4*)pWqh, n8);
        f2h_kernel<<<CDIV(n8, 256), 256>>>((const float4*)Wo, (uint4*)pWoh, n8);
        n8 = (KVD * HID) / 8;
        f2h_kernel<<<CDIV(n8, 256), 256>>>((const float4*)Wk, (uint4*)pWkh, n8);
        f2h_kernel<<<CDIV(n8, 256), 256>>>((const float4*)Wv, (uint4*)pWvh, n8);
    }

    // projections
    dim3 gq(HID / GBN, MTOT / GBM);          // (16,32)
    dim3 gk(KVD / GBN, MTOT / GBM);          // (4,32)
    gemm_h<true><<<gq, 256, GEMM_SMEM>>>(pAh, pWqh, pQh, HID, HID);
    gemm_h<true><<<gk, 256, GEMM_SMEM>>>(pAh, pWkh, pKh, KVD, HID);
    gemm_h<true><<<gk, 256, GEMM_SMEM>>>(pAh, pWvh, pVh, KVD, HID);

    // RoPE (fp16 in/out, fp32 math)
    int tq = MTOT * NH * 64;
    int tk = MTOT * KVH * 64;
    rope_h_kernel<<<CDIV(tq, 256), 256>>>(pQh, pc, ps, NH, tq);
    rope_h_kernel<<<CDIV(tk, 256), 256>>>(pKh, pc, ps, KVH, tk);

    // attention
    dim3 gf(SEQ / 64, BATCH * NH);           // (32,64)
    flash_h<<<gf, 128, FLASH_SMEM>>>(pQh, pKh, pVh, pOh);

    // output projection -> fp32 d_out
    dim3 go(HID / GBN, MTOT / GBM);          // (16,32)
    gemm_h<false><<<go, 256, GEMM_SMEM>>>(pOh, pWoh, out, HID, HID);
}